// round 5
// baseline (speedup 1.0000x reference)
#include <cuda_runtime.h>
#include <math.h>

#define NN 50000
#define EE 800000
#define IN_DIM 128
#define HD 128
#define HD2 64
#define OUT_DIM 1000
#define KHOPS 10
#define EPSV 1e-5f

// ---------------- scratch (device globals; no allocation allowed) ------------
__device__ float g_Y[(size_t)NN * HD];     // pre-BN scratch (layers 1/2)
__device__ float g_H1[(size_t)NN * HD];    // layer-1 output (residual identity)
__device__ float g_H2[(size_t)NN * HD];    // layer-2 output
__device__ float g_P[(size_t)NN * HD2];    // projected 64d hop ping
__device__ float g_PB[(size_t)NN * HD2];   // hop pong
__device__ float g_O64[(size_t)NN * HD2];  // softmax-weighted accumulator (64d)
__device__ float g_H3[(size_t)NN * HD2];
__device__ float g_S1[HD], g_Q1[HD], g_S2[HD], g_Q2[HD], g_S3[HD2], g_Q3[HD2];
__device__ float g_w[KHOPS + 1];
__device__ int   g_deg[NN];
__device__ int   g_rowptr[NN + 1];
__device__ int   g_cursor[NN];
__device__ int   g_colidx[EE];

// ---------------- init: zero stats/degrees, softmax(att) ---------------------
__global__ void k_init(const float* __restrict__ att) {
    int t = blockIdx.x * blockDim.x + threadIdx.x;
    int stride = gridDim.x * blockDim.x;
    for (int i = t; i < NN; i += stride) g_deg[i] = 0;
    if (t < HD)  { g_S1[t] = 0.f; g_Q1[t] = 0.f; g_S2[t] = 0.f; g_Q2[t] = 0.f; }
    if (t < HD2) { g_S3[t] = 0.f; g_Q3[t] = 0.f; }
    if (t == 0) {
        float m = -1e30f;
        for (int i = 0; i <= KHOPS; i++) m = fmaxf(m, att[i]);
        float e[KHOPS + 1]; float s = 0.f;
        for (int i = 0; i <= KHOPS; i++) { e[i] = expf(att[i] - m); s += e[i]; }
        for (int i = 0; i <= KHOPS; i++) g_w[i] = e[i] / s;
    }
}

// ---------------- tiled GEMM: C = A[M,K] @ B[K,Nc] (+bias) -------------------
// BM=BN=128, BK=8, 256 threads, 8x8 register tile (2x2 groups of 4x4).
// A stored k-major in smem so both fragments are LDS.128.
// Optional fused BN column stats via shared partials + per-column atomics.
__global__ __launch_bounds__(256)
void k_gemm(const float* __restrict__ A, const float* __restrict__ B,
            const float* __restrict__ bias, float* __restrict__ C,
            float* __restrict__ Sp, float* __restrict__ Qp,
            int M, int Nc, int K) {
    __shared__ float As[8][132];   // [k][row], row stride 528B (16B aligned)
    __shared__ float Bs[8][132];   // [k][col]
    __shared__ float cS[128], cQ[128];
    int tid = threadIdx.x;
    int tx = tid & 15;             // 16 col groups
    int ty = tid >> 4;             // 16 row groups
    int rowBase = blockIdx.y * 128;
    int colBase = blockIdx.x * 128;
    float acc[2][2][4][4] = {};

    if (Sp && tid < 128) { cS[tid] = 0.f; cQ[tid] = 0.f; }

    // A-load mapping: thread -> (row, kquad)
    int ar = tid >> 1, akq = (tid & 1) * 4;
    // B-load mapping: thread -> (krow, 4 cols)
    int bkr = tid >> 5, bc = (tid & 31) * 4;

    for (int k0 = 0; k0 < K; k0 += 8) {
        {   // A tile: 128 rows x 8 k, one float4 per thread, store transposed
            int gr = rowBase + ar;
            float4 v = make_float4(0.f, 0.f, 0.f, 0.f);
            if (gr < M) v = *(const float4*)(A + (size_t)gr * K + k0 + akq);
            As[akq + 0][ar] = v.x; As[akq + 1][ar] = v.y;
            As[akq + 2][ar] = v.z; As[akq + 3][ar] = v.w;
        }
        {   // B tile: 8 k x 128 cols, one float4 per thread
            int gc = colBase + bc;
            const float* brow = B + (size_t)(k0 + bkr) * Nc;
            float4 v;
            if (gc + 3 < Nc) {
                v = *(const float4*)(brow + gc);
            } else {
                v.x = (gc + 0 < Nc) ? brow[gc + 0] : 0.f;
                v.y = (gc + 1 < Nc) ? brow[gc + 1] : 0.f;
                v.z = (gc + 2 < Nc) ? brow[gc + 2] : 0.f;
                v.w = (gc + 3 < Nc) ? brow[gc + 3] : 0.f;
            }
            Bs[bkr][bc] = v.x; Bs[bkr][bc + 1] = v.y;
            Bs[bkr][bc + 2] = v.z; Bs[bkr][bc + 3] = v.w;
        }
        __syncthreads();
        #pragma unroll
        for (int kk = 0; kk < 8; kk++) {
            float4 a0 = *(const float4*)&As[kk][ty * 4];
            float4 a1 = *(const float4*)&As[kk][ty * 4 + 64];
            float4 b0 = *(const float4*)&Bs[kk][tx * 4];
            float4 b1 = *(const float4*)&Bs[kk][tx * 4 + 64];
            float ar4[2][4] = {{a0.x, a0.y, a0.z, a0.w}, {a1.x, a1.y, a1.z, a1.w}};
            float br4[2][4] = {{b0.x, b0.y, b0.z, b0.w}, {b1.x, b1.y, b1.z, b1.w}};
            #pragma unroll
            for (int h = 0; h < 2; h++)
                #pragma unroll
                for (int g = 0; g < 2; g++)
                    #pragma unroll
                    for (int i = 0; i < 4; i++)
                        #pragma unroll
                        for (int j = 0; j < 4; j++)
                            acc[h][g][i][j] = fmaf(ar4[h][i], br4[g][j], acc[h][g][i][j]);
        }
        __syncthreads();
    }
    // epilogue: store + optional fused stats
    #pragma unroll
    for (int h = 0; h < 2; h++) {
        #pragma unroll
        for (int i = 0; i < 4; i++) {
            int r = rowBase + ty * 4 + i + h * 64;
            if (r >= M) continue;
            #pragma unroll
            for (int g = 0; g < 2; g++) {
                #pragma unroll
                for (int j = 0; j < 4; j++) {
                    int c = colBase + tx * 4 + j + g * 64;
                    if (c < Nc) {
                        float v = acc[h][g][i][j];
                        if (bias) v += bias[c];
                        C[(size_t)r * Nc + c] = v;
                    }
                }
            }
        }
    }
    if (Sp) {
        #pragma unroll
        for (int g = 0; g < 2; g++) {
            float s[4] = {0.f, 0.f, 0.f, 0.f};
            float q[4] = {0.f, 0.f, 0.f, 0.f};
            #pragma unroll
            for (int h = 0; h < 2; h++)
                #pragma unroll
                for (int i = 0; i < 4; i++) {
                    int r = rowBase + ty * 4 + i + h * 64;
                    if (r >= M) continue;
                    #pragma unroll
                    for (int j = 0; j < 4; j++) {
                        float v = acc[h][g][i][j];
                        s[j] += v; q[j] += v * v;
                    }
                }
            #pragma unroll
            for (int j = 0; j < 4; j++) {
                atomicAdd(&cS[tx * 4 + j + g * 64], s[j]);
                atomicAdd(&cQ[tx * 4 + j + g * 64], q[j]);
            }
        }
        __syncthreads();
        if (tid < 128) {
            int c = colBase + tid;
            if (c < Nc) {
                atomicAdd(Sp + c, cS[tid]);
                atomicAdd(Qp + c, cQ[tid]);
            }
        }
    }
}

// ---------------- BN apply + ReLU (+residual), vectorized float4 -------------
__global__ __launch_bounds__(256)
void k_apply(const float* __restrict__ Y, const float* __restrict__ g,
             const float* __restrict__ be, const float* __restrict__ S,
             const float* __restrict__ Q, float* __restrict__ H,
             const float* __restrict__ resid, int M, int C) {
    __shared__ float4 sc4[32], sh4[32];
    int tid = threadIdx.x;
    int c4 = C >> 2;
    if (tid < c4) {
        float4 s4, h4;
        float* sp = (float*)&s4;
        float* hp = (float*)&h4;
        #pragma unroll
        for (int k = 0; k < 4; k++) {
            int col = tid * 4 + k;
            float mean = S[col] / (float)M;
            float var = Q[col] / (float)M - mean * mean;
            float rstd = rsqrtf(var + EPSV);
            float scale = g[col] * rstd;
            sp[k] = scale;
            hp[k] = be[col] - mean * scale;
        }
        sc4[tid] = s4; sh4[tid] = h4;
    }
    __syncthreads();
    int total = M * c4;
    int stride = gridDim.x * blockDim.x;
    int mask = c4 - 1;  // c4 is 16 or 32 (power of two)
    for (int idx = blockIdx.x * blockDim.x + tid; idx < total; idx += stride) {
        int j4 = idx & mask;
        float4 y = ((const float4*)Y)[idx];
        float4 sc = sc4[j4], sh = sh4[j4];
        float4 r;
        r.x = fmaxf(fmaf(y.x, sc.x, sh.x), 0.f);
        r.y = fmaxf(fmaf(y.y, sc.y, sh.y), 0.f);
        r.z = fmaxf(fmaf(y.z, sc.z, sh.z), 0.f);
        r.w = fmaxf(fmaf(y.w, sc.w, sh.w), 0.f);
        if (resid) {
            float4 rr = ((const float4*)resid)[idx];
            r.x += rr.x; r.y += rr.y; r.z += rr.z; r.w += rr.w;
        }
        ((float4*)H)[idx] = r;
    }
}

// ---------------- column stats for OUT64 (final BN) --------------------------
__global__ __launch_bounds__(256)
void k_stats64(const float* __restrict__ Y, float* __restrict__ S,
               float* __restrict__ Q, int M) {
    int col = threadIdx.x & 63;
    int rg = threadIdx.x >> 6;  // 0..3
    float s = 0.f, q = 0.f;
    for (int r = blockIdx.x * 4 + rg; r < M; r += gridDim.x * 4) {
        float v = Y[(size_t)r * HD2 + col];
        s += v; q += v * v;
    }
    atomicAdd(S + col, s);
    atomicAdd(Q + col, q);
}

// ---------------- CSR build: histogram -> scan -> scatter --------------------
__global__ void k_hist(const int* __restrict__ dst) {
    int t = blockIdx.x * blockDim.x + threadIdx.x;
    int stride = gridDim.x * blockDim.x;
    for (int e = t; e < EE; e += stride) atomicAdd(&g_deg[dst[e]], 1);
}

__global__ void k_scan() {  // one block, 1024 threads
    __shared__ int ss[1024];
    int t = threadIdx.x;
    const int CH = (NN + 1023) / 1024;
    int lo = t * CH;
    int hi = lo + CH; if (hi > NN) hi = NN;
    int loc = 0;
    for (int i = lo; i < hi; i++) loc += g_deg[i];
    ss[t] = loc;
    __syncthreads();
    for (int off = 1; off < 1024; off <<= 1) {
        int v = (t >= off) ? ss[t - off] : 0;
        __syncthreads();
        ss[t] += v;
        __syncthreads();
    }
    int run = ss[t] - loc;  // exclusive prefix
    for (int i = lo; i < hi; i++) {
        g_rowptr[i] = run;
        g_cursor[i] = run;
        run += g_deg[i];
    }
    if (t == 1023) g_rowptr[NN] = ss[1023];
}

__global__ void k_scatter(const int* __restrict__ src, const int* __restrict__ dst) {
    int t = blockIdx.x * blockDim.x + threadIdx.x;
    int stride = gridDim.x * blockDim.x;
    for (int e = t; e < EE; e += stride) {
        int d = dst[e];
        int p = atomicAdd(&g_cursor[d], 1);
        g_colidx[p] = src[e];
    }
}

// ---------------- 64d propagation hop: half-warp-per-dst gather-reduce -------
// nxt[d] = sum_{in-edges} cur[src];  O64[d] = (hop==0 ? w0*cur[d] : O64[d]) + w[hop+1]*nxt[d]
__global__ __launch_bounds__(256)
void k_hop64(int hop) {
    const float* __restrict__ cur = (hop & 1) ? g_PB : g_P;
    float* __restrict__ nxt       = (hop & 1) ? g_P : g_PB;
    int gid = blockIdx.x * blockDim.x + threadIdx.x;
    int d = gid >> 4;            // half-warp per destination node
    int lane = threadIdx.x & 15;
    if (d >= NN) return;
    float w = g_w[hop + 1];
    int s = g_rowptr[d];
    int e = g_rowptr[d + 1];
    float4 acc0 = make_float4(0.f, 0.f, 0.f, 0.f);
    float4 acc1 = make_float4(0.f, 0.f, 0.f, 0.f);
    float4 acc2 = make_float4(0.f, 0.f, 0.f, 0.f);
    float4 acc3 = make_float4(0.f, 0.f, 0.f, 0.f);
    int i = s;
    for (; i + 3 < e; i += 4) {
        int s0 = __ldg(&g_colidx[i]);
        int s1 = __ldg(&g_colidx[i + 1]);
        int s2 = __ldg(&g_colidx[i + 2]);
        int s3 = __ldg(&g_colidx[i + 3]);
        float4 v0 = *(const float4*)(cur + (size_t)s0 * HD2 + lane * 4);
        float4 v1 = *(const float4*)(cur + (size_t)s1 * HD2 + lane * 4);
        float4 v2 = *(const float4*)(cur + (size_t)s2 * HD2 + lane * 4);
        float4 v3 = *(const float4*)(cur + (size_t)s3 * HD2 + lane * 4);
        acc0.x += v0.x; acc0.y += v0.y; acc0.z += v0.z; acc0.w += v0.w;
        acc1.x += v1.x; acc1.y += v1.y; acc1.z += v1.z; acc1.w += v1.w;
        acc2.x += v2.x; acc2.y += v2.y; acc2.z += v2.z; acc2.w += v2.w;
        acc3.x += v3.x; acc3.y += v3.y; acc3.z += v3.z; acc3.w += v3.w;
    }
    for (; i < e; i++) {
        int s0 = __ldg(&g_colidx[i]);
        float4 v0 = *(const float4*)(cur + (size_t)s0 * HD2 + lane * 4);
        acc0.x += v0.x; acc0.y += v0.y; acc0.z += v0.z; acc0.w += v0.w;
    }
    float4 a = make_float4((acc0.x + acc1.x) + (acc2.x + acc3.x),
                           (acc0.y + acc1.y) + (acc2.y + acc3.y),
                           (acc0.z + acc1.z) + (acc2.z + acc3.z),
                           (acc0.w + acc1.w) + (acc2.w + acc3.w));
    size_t base = (size_t)d * HD2 + lane * 4;
    *(float4*)(nxt + base) = a;
    float4 o;
    if (hop == 0) {
        float w0 = g_w[0];
        float4 c = *(const float4*)(cur + base);
        o = make_float4(w0 * c.x, w0 * c.y, w0 * c.z, w0 * c.w);
    } else {
        o = *(float4*)(g_O64 + base);
    }
    o.x += w * a.x; o.y += w * a.y; o.z += w * a.z; o.w += w * a.w;
    *(float4*)(g_O64 + base) = o;
}

// ---------------- host launcher ----------------------------------------------
extern "C" void kernel_launch(void* const* d_in, const int* in_sizes, int n_in,
                              void* d_out, int out_size) {
    const float* x    = (const float*)d_in[0];
    const int*   ei   = (const int*)d_in[1];
    const float* W1   = (const float*)d_in[2];
    const float* g1   = (const float*)d_in[4];
    const float* be1  = (const float*)d_in[5];
    const float* W2   = (const float*)d_in[6];
    const float* g2   = (const float*)d_in[8];
    const float* be2  = (const float*)d_in[9];
    const float* att  = (const float*)d_in[10];
    const float* W3   = (const float*)d_in[11];
    const float* g3   = (const float*)d_in[13];
    const float* be3  = (const float*)d_in[14];
    const float* Wout = (const float*)d_in[15];
    const float* bout = (const float*)d_in[16];
    // b1/b2/b3 dropped: BN is invariant to per-column constant shifts.
    const int* srcp = ei;
    const int* dstp = ei + EE;
    float* out = (float*)d_out;

    float *Y, *H1, *H2, *P, *O64, *H3, *S1, *Q1, *S2, *Q2, *S3, *Q3;
    cudaGetSymbolAddress((void**)&Y,   g_Y);
    cudaGetSymbolAddress((void**)&H1,  g_H1);
    cudaGetSymbolAddress((void**)&H2,  g_H2);
    cudaGetSymbolAddress((void**)&P,   g_P);
    cudaGetSymbolAddress((void**)&O64, g_O64);
    cudaGetSymbolAddress((void**)&H3,  g_H3);
    cudaGetSymbolAddress((void**)&S1,  g_S1);
    cudaGetSymbolAddress((void**)&Q1,  g_Q1);
    cudaGetSymbolAddress((void**)&S2,  g_S2);
    cudaGetSymbolAddress((void**)&Q2,  g_Q2);
    cudaGetSymbolAddress((void**)&S3,  g_S3);
    cudaGetSymbolAddress((void**)&Q3,  g_Q3);

    const int MB = (NN + 127) / 128;  // 391 row-tiles

    k_init<<<200, 256>>>(att);

    // CSR by destination (independent of MLP; do it early)
    k_hist<<<1024, 256>>>(dstp);
    k_scan<<<1, 1024>>>();
    k_scatter<<<1024, 256>>>(srcp, dstp);

    // layer 1: h1 = relu(bn(x @ W1))           [stats fused in GEMM]
    k_gemm<<<dim3(1, MB), 256>>>(x, W1, nullptr, Y, S1, Q1, NN, HD, IN_DIM);
    k_apply<<<2048, 256>>>(Y, g1, be1, S1, Q1, H1, nullptr, NN, HD);

    // layer 2: h2 = relu(bn(h1 @ W2)) + h1     [stats fused in GEMM]
    k_gemm<<<dim3(1, MB), 256>>>(H1, W2, nullptr, Y, S2, Q2, NN, HD, HD);
    k_apply<<<2048, 256>>>(Y, g2, be2, S2, Q2, H2, H1, NN, HD);

    // project to 64d BEFORE propagation: P = h2 @ W3  (A^i and W3 commute)
    k_gemm<<<dim3(1, MB), 256>>>(H2, W3, nullptr, P, nullptr, nullptr, NN, HD2, HD);

    // K hops in 64d; weighted accumulation fused (hop 0 seeds O64 = w0*P)
    for (int h = 0; h < KHOPS; h++)
        k_hop64<<<(NN * 16 + 255) / 256, 256>>>(h);

    // output MLP: h3 = relu(bn(O64)); out = h3 @ Wout + bout
    k_stats64<<<1024, 256>>>(O64, S3, Q3, NN);
    k_apply<<<2048, 256>>>(O64, g3, be3, S3, Q3, H3, nullptr, NN, HD2);
    k_gemm<<<dim3((OUT_DIM + 127) / 128, MB), 256>>>(H3, Wout, bout, out,
                                                     nullptr, nullptr, NN, OUT_DIM, HD2);
}